// round 11
// baseline (speedup 1.0000x reference)
#include <cuda_runtime.h>
#include <cuda_fp16.h>
#include <cstdint>

#define K_DIM 256
#define N_DIM 256
#define MAX_NODES 100000
#define MAX_EDGES 800000
#define SCAN_BLK 1024
#define MAX_SCAN_BLOCKS ((MAX_NODES + SCAN_BLK - 1) / SCAN_BLK)

// Static device scratch (allocation-free rule)
__device__ float g_supp[(size_t)MAX_NODES * N_DIM];
__device__ __half g_wh[K_DIM * N_DIM];           // W fp16, B-operand layout [n][k]
__device__ int   g_deg[MAX_NODES];
__device__ int   g_off[MAX_NODES];
__device__ int   g_rank[MAX_EDGES];
__device__ int   g_bsum[MAX_SCAN_BLOCKS];
__device__ int   g_src_s[MAX_EDGES];
__device__ float g_w_s[MAX_EDGES];

// ---------------------------------------------------------------------------
// helpers
// ---------------------------------------------------------------------------
__device__ __forceinline__ uint32_t smem_u32(const void* p) {
    uint32_t a;
    asm("{ .reg .u64 t; cvta.to.shared.u64 t, %1; cvt.u32.u64 %0, t; }" : "=r"(a) : "l"(p));
    return a;
}
__device__ __forceinline__ void cp16(uint32_t dst, const void* src) {
    asm volatile("cp.async.cg.shared.global [%0], [%1], 16;"
                 :: "r"(dst), "l"(src) : "memory");
}
#define CP_COMMIT() asm volatile("cp.async.commit_group;" ::: "memory")
#define CP_WAIT(n)  asm volatile("cp.async.wait_group %0;" :: "n"(n) : "memory")

__device__ __forceinline__ void ldm_x4(uint32_t addr, uint32_t r[4]) {
    asm volatile("ldmatrix.sync.aligned.m8n8.x4.shared.b16 {%0,%1,%2,%3}, [%4];"
                 : "=r"(r[0]), "=r"(r[1]), "=r"(r[2]), "=r"(r[3]) : "r"(addr));
}
__device__ __forceinline__ void mma_f16(float c[4], const uint32_t a[4],
                                        uint32_t b0, uint32_t b1) {
    asm volatile(
        "mma.sync.aligned.m16n8k16.row.col.f32.f16.f16.f32 "
        "{%0,%1,%2,%3}, {%4,%5,%6,%7}, {%8,%9}, {%0,%1,%2,%3};"
        : "+f"(c[0]), "+f"(c[1]), "+f"(c[2]), "+f"(c[3])
        : "r"(a[0]), "r"(a[1]), "r"(a[2]), "r"(a[3]), "r"(b0), "r"(b1));
}
__device__ __forceinline__ uint32_t pack_h2(float x, float y) {
    __half2 h = __floats2half2_rn(x, y);
    return *reinterpret_cast<uint32_t*>(&h);
}

// ---------------------------------------------------------------------------
// Kernel 0: convert + transpose W -> fp16, B-operand layout [n][k]
// ---------------------------------------------------------------------------
__global__ void convert_w_kernel(const float* __restrict__ W,
                                 __half* __restrict__ wh) {
    int k = blockIdx.x;
    int n = threadIdx.x;
    wh[n * K_DIM + k] = __float2half(W[k * N_DIM + n]);
}

// ---------------------------------------------------------------------------
// CSR build: zero -> hist(+rank) -> scan(3) -> scatter
// ---------------------------------------------------------------------------
__global__ void zero_deg_kernel(int* __restrict__ deg, int N) {
    int i = blockIdx.x * blockDim.x + threadIdx.x;
    if (i < N) deg[i] = 0;
}
__global__ void hist_rank_kernel(const int* __restrict__ edst,
                                 int* __restrict__ deg,
                                 int* __restrict__ rank, int E) {
    int i = blockIdx.x * blockDim.x + threadIdx.x;
    if (i < E) rank[i] = atomicAdd(&deg[edst[i]], 1);
}
__global__ __launch_bounds__(SCAN_BLK) void scan1_kernel(
    const int* __restrict__ deg, int* __restrict__ off, int* __restrict__ bsum, int N) {
    __shared__ int s[SCAN_BLK];
    int tid = threadIdx.x;
    int gid = blockIdx.x * SCAN_BLK + tid;
    int v = (gid < N) ? deg[gid] : 0;
    s[tid] = v;
    __syncthreads();
#pragma unroll
    for (int d = 1; d < SCAN_BLK; d <<= 1) {
        int t = (tid >= d) ? s[tid - d] : 0;
        __syncthreads();
        s[tid] += t;
        __syncthreads();
    }
    if (gid < N) off[gid] = s[tid] - v;
    if (tid == SCAN_BLK - 1) bsum[blockIdx.x] = s[tid];
}
__global__ __launch_bounds__(SCAN_BLK) void scan2_kernel(int* __restrict__ bsum, int nb) {
    __shared__ int s[SCAN_BLK];
    int tid = threadIdx.x;
    int v = (tid < nb) ? bsum[tid] : 0;
    s[tid] = v;
    __syncthreads();
#pragma unroll
    for (int d = 1; d < SCAN_BLK; d <<= 1) {
        int t = (tid >= d) ? s[tid - d] : 0;
        __syncthreads();
        s[tid] += t;
        __syncthreads();
    }
    if (tid < nb) bsum[tid] = s[tid] - v;
}
__global__ void scan3_kernel(int* __restrict__ off, const int* __restrict__ bsum, int N) {
    int gid = blockIdx.x * blockDim.x + threadIdx.x;
    if (gid < N) off[gid] += bsum[gid / SCAN_BLK];
}
__global__ void scatter_kernel(const int* __restrict__ esrc,
                               const int* __restrict__ edst,
                               const float* __restrict__ ew,
                               const int* __restrict__ off,
                               const int* __restrict__ rank,
                               int* __restrict__ src_s,
                               float* __restrict__ w_s, int E) {
    int e = blockIdx.x * blockDim.x + threadIdx.x;
    if (e < E) {
        int pos = off[edst[e]] + rank[e];
        src_s[pos] = esrc[e];
        w_s[pos] = ew[e];
    }
}

// ---------------------------------------------------------------------------
// Aggregate: one warp per dst node (at L2 gather floor — do not touch)
// ---------------------------------------------------------------------------
__global__ __launch_bounds__(256) void agg_kernel(
    const float* __restrict__ supp,
    const int* __restrict__ src_s,
    const float* __restrict__ w_s,
    const int* __restrict__ off,
    const float* __restrict__ bias,
    float* __restrict__ out,
    int N, int E) {

    const int warp = (blockIdx.x * blockDim.x + threadIdx.x) >> 5;
    const int lane = threadIdx.x & 31;
    if (warp >= N) return;

    const int beg = off[warp];
    const int end = (warp + 1 < N) ? off[warp + 1] : E;

    const float4* bias4 = reinterpret_cast<const float4*>(bias);
    float4 acc0 = bias4[lane * 2];
    float4 acc1 = bias4[lane * 2 + 1];

    for (int j = beg; j < end; ++j) {
        const int src = __ldg(&src_s[j]);
        const float w = __ldg(&w_s[j]);
        const float4* srow = reinterpret_cast<const float4*>(supp + (size_t)src * N_DIM);
        float4 a = __ldg(&srow[lane * 2]);
        float4 b = __ldg(&srow[lane * 2 + 1]);
        acc0.x = fmaf(a.x, w, acc0.x); acc0.y = fmaf(a.y, w, acc0.y);
        acc0.z = fmaf(a.z, w, acc0.z); acc0.w = fmaf(a.w, w, acc0.w);
        acc1.x = fmaf(b.x, w, acc1.x); acc1.y = fmaf(b.y, w, acc1.y);
        acc1.z = fmaf(b.z, w, acc1.z); acc1.w = fmaf(b.w, w, acc1.w);
    }

    float4* drow = reinterpret_cast<float4*>(out + (size_t)warp * N_DIM);
    drow[lane * 2] = acc0;
    drow[lane * 2 + 1] = acc1;
}

// ---------------------------------------------------------------------------
// GEMM: single-product fp16.  BM=128, BN=128, BK=32, double-buffer, occ 4.
// A: f32 LDG -> fp16 cvt -> STS.  B: cp.async.  1 HMMA product (vs 3 before).
// smem rows stride 80B (64B data + 16B pad): conflict-free LDSM.
// ---------------------------------------------------------------------------
#define BK2 32
#define ROWB 80
#define T128 (128 * ROWB)
#define O_AH 0
#define O_BH (T128)
#define STG (2 * T128)                /* 20480 */
#define GEMM_SMEM (2 * STG)           /* 40960 -> 4+ CTAs/SM */

__global__ __launch_bounds__(256, 4) void gemm_f16_kernel(
    const float* __restrict__ x,
    const __half* __restrict__ wh,
    float* __restrict__ supp, int M) {

    extern __shared__ __align__(128) char smem[];
    const uint32_t sbase = smem_u32(smem);

    const int tid = threadIdx.x;
    const int wid = tid >> 5;
    const int lane = tid & 31;
    const int rowBase = blockIdx.y * 128;
    const int colBase = blockIdx.x * 128;

    const int warp_m = (wid >> 2) * 64;
    const int warp_n = (wid & 3) * 32;

    const int ld_row = tid >> 1;
    const int ld_kc  = (tid & 1) * 16;
    const int a_grow = rowBase + ld_row;
    const bool a_ok = (a_grow < M);
    const float4* x4 = reinterpret_cast<const float4*>(x);

    const int a_lr = lane & 15;
    const int a_lk = (lane >> 4) * 8;
    const int b_ln = ((lane >> 4) * 8) + (lane & 7);
    const int b_lk = ((lane >> 3) & 1) * 8;

    float acc[4][4][4];
#pragma unroll
    for (int i = 0; i < 4; i++)
#pragma unroll
        for (int j = 0; j < 4; j++)
#pragma unroll
            for (int q = 0; q < 4; q++) acc[i][j][q] = 0.0f;

    float4 ga[4];

    auto load_A = [&](int c) {
        const int k0 = c * BK2;
#pragma unroll
        for (int j = 0; j < 4; j++) {
            ga[j] = a_ok ? x4[(size_t)a_grow * (K_DIM / 4) + ((k0 + ld_kc) >> 2) + j]
                         : make_float4(0.f, 0.f, 0.f, 0.f);
        }
    };
    auto store_A = [&](int s) {
        const uint32_t st = sbase + s * STG;
        uint32_t a_off = (uint32_t)ld_row * ROWB + ld_kc * 2;
#pragma unroll
        for (int j = 0; j < 4; j++) {
            uint32_t h0 = pack_h2(ga[j].x, ga[j].y);
            uint32_t h1 = pack_h2(ga[j].z, ga[j].w);
            asm volatile("st.shared.v2.b32 [%0], {%1, %2};"
                         :: "r"(st + O_AH + a_off + j * 8), "r"(h0), "r"(h1) : "memory");
        }
    };
    auto issue_B = [&](int s, int c) {
        const int k0 = c * BK2;
        const uint32_t st = sbase + s * STG;
        {
            int row = tid >> 1, cc = tid & 1;          // 128 rows x 2 chunks? no:
        }
        // 128 rows x 4 16B-chunks = 512 chunks; 256 threads -> 2 each
#pragma unroll
        for (int i = 0; i < 2; i++) {
            int a = tid + i * 256;
            int row = a >> 2, cc = a & 3;
            const __half* sh = wh + (size_t)(colBase + row) * K_DIM + k0 + cc * 8;
            cp16(st + O_BH + row * ROWB + cc * 16, sh);
        }
        CP_COMMIT();
    };

    auto compute = [&](int s) {
        const uint32_t st = sbase + s * STG;
#pragma unroll
        for (int ks = 0; ks < 2; ks++) {
            uint32_t ah[4][4];
#pragma unroll
            for (int mi = 0; mi < 4; mi++) {
                uint32_t off = (uint32_t)(warp_m + mi * 16 + a_lr) * ROWB +
                               (ks * 16 + a_lk) * 2;
                ldm_x4(st + O_AH + off, ah[mi]);
            }
#pragma unroll
            for (int pi = 0; pi < 2; pi++) {
                uint32_t off = (uint32_t)(warp_n + pi * 16 + b_ln) * ROWB +
                               (ks * 16 + b_lk) * 2;
                uint32_t bh[4];
                ldm_x4(st + O_BH + off, bh);
#pragma unroll
                for (int mi = 0; mi < 4; mi++) {
                    mma_f16(acc[mi][pi * 2 + 0], ah[mi], bh[0], bh[1]);
                    mma_f16(acc[mi][pi * 2 + 1], ah[mi], bh[2], bh[3]);
                }
            }
        }
    };

    // prologue
    load_A(0);
    store_A(0);
    issue_B(0, 0);

    // Single-sync pipeline: top-of-iter sync => compute(c-1) done by all
    // warps, so buffer (c+1)&1 is free; store_A(c) writes visible.
#pragma unroll 1
    for (int c = 0; c < K_DIM / BK2; ++c) {
        const bool more = (c + 1 < K_DIM / BK2);
        CP_WAIT(0);                    // B(c) landed
        __syncthreads();
        if (more) {
            load_A(c + 1);             // LDG overlaps compute(c)
            issue_B((c + 1) & 1, c + 1);
        }
        compute(c & 1);
        if (more) store_A((c + 1) & 1);
    }

    // epilogue
    const int lrow = lane >> 2;
    const int lcol = (lane & 3) * 2;
#pragma unroll
    for (int mi = 0; mi < 4; mi++) {
#pragma unroll
        for (int half = 0; half < 2; half++) {
            int grow = rowBase + warp_m + mi * 16 + lrow + half * 8;
            if (grow < M) {
                float* dst = supp + (size_t)grow * N_DIM + colBase + warp_n;
#pragma unroll
                for (int ni = 0; ni < 4; ni++) {
                    float2 v = half ? make_float2(acc[mi][ni][2], acc[mi][ni][3])
                                    : make_float2(acc[mi][ni][0], acc[mi][ni][1]);
                    *reinterpret_cast<float2*>(dst + ni * 8 + lcol) = v;
                }
            }
        }
    }
}

// ---------------------------------------------------------------------------
// Launch — CSR build forked on side stream, overlapped with convert+GEMM.
// ---------------------------------------------------------------------------
extern "C" void kernel_launch(void* const* d_in, const int* in_sizes, int n_in,
                              void* d_out, int out_size) {
    const float* x      = (const float*)d_in[0];
    const float* weight = (const float*)d_in[1];
    const float* bias   = (const float*)d_in[2];
    const float* ew     = (const float*)d_in[3];
    const int*   esrc   = (const int*)d_in[4];
    const int*   edst   = (const int*)d_in[5];
    float* out = (float*)d_out;

    const int M = in_sizes[0] / K_DIM;   // 100000
    const int E = in_sizes[3];           // 800000

    float* supp;          cudaGetSymbolAddress((void**)&supp, g_supp);
    __half* wh;           cudaGetSymbolAddress((void**)&wh, g_wh);
    int* deg;             cudaGetSymbolAddress((void**)&deg, g_deg);
    int* off;             cudaGetSymbolAddress((void**)&off, g_off);
    int* rank;            cudaGetSymbolAddress((void**)&rank, g_rank);
    int* bsum;            cudaGetSymbolAddress((void**)&bsum, g_bsum);
    int* src_s;           cudaGetSymbolAddress((void**)&src_s, g_src_s);
    float* w_s;           cudaGetSymbolAddress((void**)&w_s, g_w_s);

    static cudaStream_t s_side = nullptr;
    static cudaEvent_t  s_fork = nullptr, s_join = nullptr;
    static bool s_init = false;
    if (!s_init) {
        cudaFuncSetAttribute(gemm_f16_kernel,
                             cudaFuncAttributeMaxDynamicSharedMemorySize, GEMM_SMEM);
        cudaStreamCreateWithFlags(&s_side, cudaStreamNonBlocking);
        cudaEventCreateWithFlags(&s_fork, cudaEventDisableTiming);
        cudaEventCreateWithFlags(&s_join, cudaEventDisableTiming);
        s_init = true;
    }

    const int nblk_scan = (M + SCAN_BLK - 1) / SCAN_BLK;

    // Fork
    cudaEventRecord(s_fork, 0);
    cudaStreamWaitEvent(s_side, s_fork, 0);

    // side stream: CSR build
    zero_deg_kernel<<<(M + 255) / 256, 256, 0, s_side>>>(deg, M);
    hist_rank_kernel<<<(E + 255) / 256, 256, 0, s_side>>>(edst, deg, rank, E);
    scan1_kernel<<<nblk_scan, SCAN_BLK, 0, s_side>>>(deg, off, bsum, M);
    scan2_kernel<<<1, SCAN_BLK, 0, s_side>>>(bsum, nblk_scan);
    scan3_kernel<<<(M + 255) / 256, 256, 0, s_side>>>(off, bsum, M);
    scatter_kernel<<<(E + 255) / 256, 256, 0, s_side>>>(esrc, edst, ew, off, rank,
                                                        src_s, w_s, E);
    cudaEventRecord(s_join, s_side);

    // main stream: convert W, GEMM
    convert_w_kernel<<<K_DIM, N_DIM>>>(weight, wh);
    {
        dim3 grid(N_DIM / 128, (M + 127) / 128);
        gemm_f16_kernel<<<grid, 256, GEMM_SMEM>>>(x, wh, supp, M);
    }

    // Join, then aggregate
    cudaStreamWaitEvent(0, s_join, 0);
    {
        int blocks = (M + 7) / 8;
        agg_kernel<<<blocks, 256>>>(supp, src_s, w_s, off, bias, out, M, E);
    }
}

// round 12
// speedup vs baseline: 1.6493x; 1.6493x over previous
#include <cuda_runtime.h>
#include <cuda_fp16.h>
#include <cstdint>

#define K_DIM 256
#define N_DIM 256
#define MAX_NODES 100000
#define MAX_EDGES 800000
#define SCAN_BLK 1024
#define MAX_SCAN_BLOCKS ((MAX_NODES + SCAN_BLK - 1) / SCAN_BLK)

// Static device scratch (allocation-free rule)
__device__ float g_supp[(size_t)MAX_NODES * N_DIM];
__device__ __half g_wh[K_DIM * N_DIM];           // W fp16, B-operand layout [n][k]
__device__ int   g_deg[MAX_NODES];
__device__ int   g_off[MAX_NODES];
__device__ int   g_rank[MAX_EDGES];
__device__ int   g_bsum[MAX_SCAN_BLOCKS];
__device__ int   g_src_s[MAX_EDGES];
__device__ float g_w_s[MAX_EDGES];

// ---------------------------------------------------------------------------
// helpers
// ---------------------------------------------------------------------------
__device__ __forceinline__ uint32_t smem_u32(const void* p) {
    uint32_t a;
    asm("{ .reg .u64 t; cvta.to.shared.u64 t, %1; cvt.u32.u64 %0, t; }" : "=r"(a) : "l"(p));
    return a;
}
__device__ __forceinline__ void cp16(uint32_t dst, const void* src) {
    asm volatile("cp.async.cg.shared.global [%0], [%1], 16;"
                 :: "r"(dst), "l"(src) : "memory");
}
#define CP_COMMIT() asm volatile("cp.async.commit_group;" ::: "memory")
#define CP_WAIT(n)  asm volatile("cp.async.wait_group %0;" :: "n"(n) : "memory")

__device__ __forceinline__ void ldm_x4(uint32_t addr, uint32_t r[4]) {
    asm volatile("ldmatrix.sync.aligned.m8n8.x4.shared.b16 {%0,%1,%2,%3}, [%4];"
                 : "=r"(r[0]), "=r"(r[1]), "=r"(r[2]), "=r"(r[3]) : "r"(addr));
}
__device__ __forceinline__ void mma_f16(float c[4], const uint32_t a[4],
                                        uint32_t b0, uint32_t b1) {
    asm volatile(
        "mma.sync.aligned.m16n8k16.row.col.f32.f16.f16.f32 "
        "{%0,%1,%2,%3}, {%4,%5,%6,%7}, {%8,%9}, {%0,%1,%2,%3};"
        : "+f"(c[0]), "+f"(c[1]), "+f"(c[2]), "+f"(c[3])
        : "r"(a[0]), "r"(a[1]), "r"(a[2]), "r"(a[3]), "r"(b0), "r"(b1));
}
__device__ __forceinline__ uint32_t pack_h2(float x, float y) {
    __half2 h = __floats2half2_rn(x, y);
    return *reinterpret_cast<uint32_t*>(&h);
}

// ---------------------------------------------------------------------------
// Kernel 0: convert + transpose W -> fp16, B-operand layout [n][k]
// ---------------------------------------------------------------------------
__global__ void convert_w_kernel(const float* __restrict__ W,
                                 __half* __restrict__ wh) {
    int k = blockIdx.x;
    int n = threadIdx.x;
    wh[n * K_DIM + k] = __float2half(W[k * N_DIM + n]);
}

// ---------------------------------------------------------------------------
// CSR build: zero -> hist(+rank) -> scan(3) -> scatter
// ---------------------------------------------------------------------------
__global__ void zero_deg_kernel(int* __restrict__ deg, int N) {
    int i = blockIdx.x * blockDim.x + threadIdx.x;
    if (i < N) deg[i] = 0;
}
__global__ void hist_rank_kernel(const int* __restrict__ edst,
                                 int* __restrict__ deg,
                                 int* __restrict__ rank, int E) {
    int i = blockIdx.x * blockDim.x + threadIdx.x;
    if (i < E) rank[i] = atomicAdd(&deg[edst[i]], 1);
}
__global__ __launch_bounds__(SCAN_BLK) void scan1_kernel(
    const int* __restrict__ deg, int* __restrict__ off, int* __restrict__ bsum, int N) {
    __shared__ int s[SCAN_BLK];
    int tid = threadIdx.x;
    int gid = blockIdx.x * SCAN_BLK + tid;
    int v = (gid < N) ? deg[gid] : 0;
    s[tid] = v;
    __syncthreads();
#pragma unroll
    for (int d = 1; d < SCAN_BLK; d <<= 1) {
        int t = (tid >= d) ? s[tid - d] : 0;
        __syncthreads();
        s[tid] += t;
        __syncthreads();
    }
    if (gid < N) off[gid] = s[tid] - v;
    if (tid == SCAN_BLK - 1) bsum[blockIdx.x] = s[tid];
}
__global__ __launch_bounds__(SCAN_BLK) void scan2_kernel(int* __restrict__ bsum, int nb) {
    __shared__ int s[SCAN_BLK];
    int tid = threadIdx.x;
    int v = (tid < nb) ? bsum[tid] : 0;
    s[tid] = v;
    __syncthreads();
#pragma unroll
    for (int d = 1; d < SCAN_BLK; d <<= 1) {
        int t = (tid >= d) ? s[tid - d] : 0;
        __syncthreads();
        s[tid] += t;
        __syncthreads();
    }
    if (tid < nb) bsum[tid] = s[tid] - v;
}
__global__ void scan3_kernel(int* __restrict__ off, const int* __restrict__ bsum, int N) {
    int gid = blockIdx.x * blockDim.x + threadIdx.x;
    if (gid < N) off[gid] += bsum[gid / SCAN_BLK];
}
__global__ void scatter_kernel(const int* __restrict__ esrc,
                               const int* __restrict__ edst,
                               const float* __restrict__ ew,
                               const int* __restrict__ off,
                               const int* __restrict__ rank,
                               int* __restrict__ src_s,
                               float* __restrict__ w_s, int E) {
    int e = blockIdx.x * blockDim.x + threadIdx.x;
    if (e < E) {
        int pos = off[edst[e]] + rank[e];
        src_s[pos] = esrc[e];
        w_s[pos] = ew[e];
    }
}

// ---------------------------------------------------------------------------
// Aggregate: one warp per dst node (at L2 gather floor — do not touch)
// ---------------------------------------------------------------------------
__global__ __launch_bounds__(256) void agg_kernel(
    const float* __restrict__ supp,
    const int* __restrict__ src_s,
    const float* __restrict__ w_s,
    const int* __restrict__ off,
    const float* __restrict__ bias,
    float* __restrict__ out,
    int N, int E) {

    const int warp = (blockIdx.x * blockDim.x + threadIdx.x) >> 5;
    const int lane = threadIdx.x & 31;
    if (warp >= N) return;

    const int beg = off[warp];
    const int end = (warp + 1 < N) ? off[warp + 1] : E;

    const float4* bias4 = reinterpret_cast<const float4*>(bias);
    float4 acc0 = bias4[lane * 2];
    float4 acc1 = bias4[lane * 2 + 1];

    for (int j = beg; j < end; ++j) {
        const int src = __ldg(&src_s[j]);
        const float w = __ldg(&w_s[j]);
        const float4* srow = reinterpret_cast<const float4*>(supp + (size_t)src * N_DIM);
        float4 a = __ldg(&srow[lane * 2]);
        float4 b = __ldg(&srow[lane * 2 + 1]);
        acc0.x = fmaf(a.x, w, acc0.x); acc0.y = fmaf(a.y, w, acc0.y);
        acc0.z = fmaf(a.z, w, acc0.z); acc0.w = fmaf(a.w, w, acc0.w);
        acc1.x = fmaf(b.x, w, acc1.x); acc1.y = fmaf(b.y, w, acc1.y);
        acc1.z = fmaf(b.z, w, acc1.z); acc1.w = fmaf(b.w, w, acc1.w);
    }

    float4* drow = reinterpret_cast<float4*>(out + (size_t)warp * N_DIM);
    drow[lane * 2] = acc0;
    drow[lane * 2 + 1] = acc1;
}

// ---------------------------------------------------------------------------
// GEMM: single-product fp16.  BM=128, BN=128, BK=32, double-buffer.
// __launch_bounds__(256,2): 128 regs/thread — NO SPILLS (R11's occ-4 cap of
// 64 regs spilled the 64-reg accumulator file and regressed 75us).
// ---------------------------------------------------------------------------
#define BK2 32
#define ROWB 80
#define T128 (128 * ROWB)
#define O_AH 0
#define O_BH (T128)
#define STG (2 * T128)                /* 20480 */
#define GEMM_SMEM (2 * STG)           /* 40960 */

__global__ __launch_bounds__(256, 2) void gemm_f16_kernel(
    const float* __restrict__ x,
    const __half* __restrict__ wh,
    float* __restrict__ supp, int M) {

    extern __shared__ __align__(128) char smem[];
    const uint32_t sbase = smem_u32(smem);

    const int tid = threadIdx.x;
    const int wid = tid >> 5;
    const int lane = tid & 31;
    const int rowBase = blockIdx.y * 128;
    const int colBase = blockIdx.x * 128;

    const int warp_m = (wid >> 2) * 64;
    const int warp_n = (wid & 3) * 32;

    const int ld_row = tid >> 1;
    const int ld_kc  = (tid & 1) * 16;
    const int a_grow = rowBase + ld_row;
    const bool a_ok = (a_grow < M);
    const float4* x4 = reinterpret_cast<const float4*>(x);

    const int a_lr = lane & 15;
    const int a_lk = (lane >> 4) * 8;
    const int b_ln = ((lane >> 4) * 8) + (lane & 7);
    const int b_lk = ((lane >> 3) & 1) * 8;

    float acc[4][4][4];
#pragma unroll
    for (int i = 0; i < 4; i++)
#pragma unroll
        for (int j = 0; j < 4; j++)
#pragma unroll
            for (int q = 0; q < 4; q++) acc[i][j][q] = 0.0f;

    float4 ga[4];

    auto load_A = [&](int c) {
        const int k0 = c * BK2;
#pragma unroll
        for (int j = 0; j < 4; j++) {
            ga[j] = a_ok ? x4[(size_t)a_grow * (K_DIM / 4) + ((k0 + ld_kc) >> 2) + j]
                         : make_float4(0.f, 0.f, 0.f, 0.f);
        }
    };
    auto store_A = [&](int s) {
        const uint32_t st = sbase + s * STG;
        uint32_t a_off = (uint32_t)ld_row * ROWB + ld_kc * 2;
#pragma unroll
        for (int j = 0; j < 4; j++) {
            uint32_t h0 = pack_h2(ga[j].x, ga[j].y);
            uint32_t h1 = pack_h2(ga[j].z, ga[j].w);
            asm volatile("st.shared.v2.b32 [%0], {%1, %2};"
                         :: "r"(st + O_AH + a_off + j * 8), "r"(h0), "r"(h1) : "memory");
        }
    };
    auto issue_B = [&](int s, int c) {
        const int k0 = c * BK2;
        const uint32_t st = sbase + s * STG;
        // 128 rows x 4 16B-chunks = 512 chunks; 256 threads -> 2 each
#pragma unroll
        for (int i = 0; i < 2; i++) {
            int a = tid + i * 256;
            int row = a >> 2, cc = a & 3;
            const __half* sh = wh + (size_t)(colBase + row) * K_DIM + k0 + cc * 8;
            cp16(st + O_BH + row * ROWB + cc * 16, sh);
        }
        CP_COMMIT();
    };

    auto compute = [&](int s) {
        const uint32_t st = sbase + s * STG;
#pragma unroll
        for (int ks = 0; ks < 2; ks++) {
            uint32_t ah[4][4];
#pragma unroll
            for (int mi = 0; mi < 4; mi++) {
                uint32_t off = (uint32_t)(warp_m + mi * 16 + a_lr) * ROWB +
                               (ks * 16 + a_lk) * 2;
                ldm_x4(st + O_AH + off, ah[mi]);
            }
#pragma unroll
            for (int pi = 0; pi < 2; pi++) {
                uint32_t off = (uint32_t)(warp_n + pi * 16 + b_ln) * ROWB +
                               (ks * 16 + b_lk) * 2;
                uint32_t bh[4];
                ldm_x4(st + O_BH + off, bh);
#pragma unroll
                for (int mi = 0; mi < 4; mi++) {
                    mma_f16(acc[mi][pi * 2 + 0], ah[mi], bh[0], bh[1]);
                    mma_f16(acc[mi][pi * 2 + 1], ah[mi], bh[2], bh[3]);
                }
            }
        }
    };

    // prologue
    load_A(0);
    store_A(0);
    issue_B(0, 0);

    // Single-sync pipeline: top-of-iter sync => compute(c-1) done by all
    // warps, so buffer (c+1)&1 is free; store_A(c) writes visible.
#pragma unroll 1
    for (int c = 0; c < K_DIM / BK2; ++c) {
        const bool more = (c + 1 < K_DIM / BK2);
        CP_WAIT(0);                    // B(c) landed
        __syncthreads();
        if (more) {
            load_A(c + 1);             // LDG overlaps compute(c)
            issue_B((c + 1) & 1, c + 1);
        }
        compute(c & 1);
        if (more) store_A((c + 1) & 1);
    }

    // epilogue
    const int lrow = lane >> 2;
    const int lcol = (lane & 3) * 2;
#pragma unroll
    for (int mi = 0; mi < 4; mi++) {
#pragma unroll
        for (int half = 0; half < 2; half++) {
            int grow = rowBase + warp_m + mi * 16 + lrow + half * 8;
            if (grow < M) {
                float* dst = supp + (size_t)grow * N_DIM + colBase + warp_n;
#pragma unroll
                for (int ni = 0; ni < 4; ni++) {
                    float2 v = half ? make_float2(acc[mi][ni][2], acc[mi][ni][3])
                                    : make_float2(acc[mi][ni][0], acc[mi][ni][1]);
                    *reinterpret_cast<float2*>(dst + ni * 8 + lcol) = v;
                }
            }
        }
    }
}

// ---------------------------------------------------------------------------
// Launch — CSR build forked on side stream, overlapped with convert+GEMM.
// ---------------------------------------------------------------------------
extern "C" void kernel_launch(void* const* d_in, const int* in_sizes, int n_in,
                              void* d_out, int out_size) {
    const float* x      = (const float*)d_in[0];
    const float* weight = (const float*)d_in[1];
    const float* bias   = (const float*)d_in[2];
    const float* ew     = (const float*)d_in[3];
    const int*   esrc   = (const int*)d_in[4];
    const int*   edst   = (const int*)d_in[5];
    float* out = (float*)d_out;

    const int M = in_sizes[0] / K_DIM;   // 100000
    const int E = in_sizes[3];           // 800000

    float* supp;          cudaGetSymbolAddress((void**)&supp, g_supp);
    __half* wh;           cudaGetSymbolAddress((void**)&wh, g_wh);
    int* deg;             cudaGetSymbolAddress((void**)&deg, g_deg);
    int* off;             cudaGetSymbolAddress((void**)&off, g_off);
    int* rank;            cudaGetSymbolAddress((void**)&rank, g_rank);
    int* bsum;            cudaGetSymbolAddress((void**)&bsum, g_bsum);
    int* src_s;           cudaGetSymbolAddress((void**)&src_s, g_src_s);
    float* w_s;           cudaGetSymbolAddress((void**)&w_s, g_w_s);

    static cudaStream_t s_side = nullptr;
    static cudaEvent_t  s_fork = nullptr, s_join = nullptr;
    static bool s_init = false;
    if (!s_init) {
        cudaFuncSetAttribute(gemm_f16_kernel,
                             cudaFuncAttributeMaxDynamicSharedMemorySize, GEMM_SMEM);
        cudaStreamCreateWithFlags(&s_side, cudaStreamNonBlocking);
        cudaEventCreateWithFlags(&s_fork, cudaEventDisableTiming);
        cudaEventCreateWithFlags(&s_join, cudaEventDisableTiming);
        s_init = true;
    }

    const int nblk_scan = (M + SCAN_BLK - 1) / SCAN_BLK;

    // Fork
    cudaEventRecord(s_fork, 0);
    cudaStreamWaitEvent(s_side, s_fork, 0);

    // side stream: CSR build
    zero_deg_kernel<<<(M + 255) / 256, 256, 0, s_side>>>(deg, M);
    hist_rank_kernel<<<(E + 255) / 256, 256, 0, s_side>>>(edst, deg, rank, E);
    scan1_kernel<<<nblk_scan, SCAN_BLK, 0, s_side>>>(deg, off, bsum, M);
    scan2_kernel<<<1, SCAN_BLK, 0, s_side>>>(bsum, nblk_scan);
    scan3_kernel<<<(M + 255) / 256, 256, 0, s_side>>>(off, bsum, M);
    scatter_kernel<<<(E + 255) / 256, 256, 0, s_side>>>(esrc, edst, ew, off, rank,
                                                        src_s, w_s, E);
    cudaEventRecord(s_join, s_side);

    // main stream: convert W, GEMM
    convert_w_kernel<<<K_DIM, N_DIM>>>(weight, wh);
    {
        dim3 grid(N_DIM / 128, (M + 127) / 128);
        gemm_f16_kernel<<<grid, 256, GEMM_SMEM>>>(x, wh, supp, M);
    }

    // Join, then aggregate
    cudaStreamWaitEvent(0, s_join, 0);
    {
        int blocks = (M + 7) / 8;
        agg_kernel<<<blocks, 256>>>(supp, src_s, w_s, off, bias, out, M, E);
    }
}

// round 13
// speedup vs baseline: 1.9768x; 1.1986x over previous
#include <cuda_runtime.h>
#include <cuda_fp16.h>
#include <cstdint>

#define K_DIM 256
#define N_DIM 256
#define MAX_NODES 100000
#define MAX_EDGES 800000
#define SCAN_BLK 1024
#define MAX_SCAN_BLOCKS ((MAX_NODES + SCAN_BLK - 1) / SCAN_BLK)

// Static device scratch (allocation-free rule)
__device__ __half g_supp[(size_t)MAX_NODES * N_DIM];   // fp16 supp: halves agg traffic
__device__ __half g_wh[K_DIM * N_DIM];                 // W fp16, B-operand layout [n][k]
__device__ int   g_deg[MAX_NODES];
__device__ int   g_off[MAX_NODES];
__device__ int   g_rank[MAX_EDGES];
__device__ int   g_bsum[MAX_SCAN_BLOCKS];
__device__ int   g_src_s[MAX_EDGES];
__device__ float g_w_s[MAX_EDGES];

// ---------------------------------------------------------------------------
// helpers
// ---------------------------------------------------------------------------
__device__ __forceinline__ uint32_t smem_u32(const void* p) {
    uint32_t a;
    asm("{ .reg .u64 t; cvta.to.shared.u64 t, %1; cvt.u32.u64 %0, t; }" : "=r"(a) : "l"(p));
    return a;
}
__device__ __forceinline__ void cp16(uint32_t dst, const void* src) {
    asm volatile("cp.async.cg.shared.global [%0], [%1], 16;"
                 :: "r"(dst), "l"(src) : "memory");
}
#define CP_COMMIT() asm volatile("cp.async.commit_group;" ::: "memory")
#define CP_WAIT(n)  asm volatile("cp.async.wait_group %0;" :: "n"(n) : "memory")

__device__ __forceinline__ void ldm_x4(uint32_t addr, uint32_t r[4]) {
    asm volatile("ldmatrix.sync.aligned.m8n8.x4.shared.b16 {%0,%1,%2,%3}, [%4];"
                 : "=r"(r[0]), "=r"(r[1]), "=r"(r[2]), "=r"(r[3]) : "r"(addr));
}
__device__ __forceinline__ void mma_f16(float c[4], const uint32_t a[4],
                                        uint32_t b0, uint32_t b1) {
    asm volatile(
        "mma.sync.aligned.m16n8k16.row.col.f32.f16.f16.f32 "
        "{%0,%1,%2,%3}, {%4,%5,%6,%7}, {%8,%9}, {%0,%1,%2,%3};"
        : "+f"(c[0]), "+f"(c[1]), "+f"(c[2]), "+f"(c[3])
        : "r"(a[0]), "r"(a[1]), "r"(a[2]), "r"(a[3]), "r"(b0), "r"(b1));
}
__device__ __forceinline__ uint32_t pack_h2(float x, float y) {
    __half2 h = __floats2half2_rn(x, y);
    return *reinterpret_cast<uint32_t*>(&h);
}

// ---------------------------------------------------------------------------
// Kernel 0: convert + transpose W -> fp16, B-operand layout [n][k]
// ---------------------------------------------------------------------------
__global__ void convert_w_kernel(const float* __restrict__ W,
                                 __half* __restrict__ wh) {
    int k = blockIdx.x;
    int n = threadIdx.x;
    wh[n * K_DIM + k] = __float2half(W[k * N_DIM + n]);
}

// ---------------------------------------------------------------------------
// CSR build: zero -> hist(+rank) -> scan(3) -> scatter
// ---------------------------------------------------------------------------
__global__ void zero_deg_kernel(int* __restrict__ deg, int N) {
    int i = blockIdx.x * blockDim.x + threadIdx.x;
    if (i < N) deg[i] = 0;
}
__global__ void hist_rank_kernel(const int* __restrict__ edst,
                                 int* __restrict__ deg,
                                 int* __restrict__ rank, int E) {
    int i = blockIdx.x * blockDim.x + threadIdx.x;
    if (i < E) rank[i] = atomicAdd(&deg[edst[i]], 1);
}
__global__ __launch_bounds__(SCAN_BLK) void scan1_kernel(
    const int* __restrict__ deg, int* __restrict__ off, int* __restrict__ bsum, int N) {
    __shared__ int s[SCAN_BLK];
    int tid = threadIdx.x;
    int gid = blockIdx.x * SCAN_BLK + tid;
    int v = (gid < N) ? deg[gid] : 0;
    s[tid] = v;
    __syncthreads();
#pragma unroll
    for (int d = 1; d < SCAN_BLK; d <<= 1) {
        int t = (tid >= d) ? s[tid - d] : 0;
        __syncthreads();
        s[tid] += t;
        __syncthreads();
    }
    if (gid < N) off[gid] = s[tid] - v;
    if (tid == SCAN_BLK - 1) bsum[blockIdx.x] = s[tid];
}
__global__ __launch_bounds__(SCAN_BLK) void scan2_kernel(int* __restrict__ bsum, int nb) {
    __shared__ int s[SCAN_BLK];
    int tid = threadIdx.x;
    int v = (tid < nb) ? bsum[tid] : 0;
    s[tid] = v;
    __syncthreads();
#pragma unroll
    for (int d = 1; d < SCAN_BLK; d <<= 1) {
        int t = (tid >= d) ? s[tid - d] : 0;
        __syncthreads();
        s[tid] += t;
        __syncthreads();
    }
    if (tid < nb) bsum[tid] = s[tid] - v;
}
__global__ void scan3_kernel(int* __restrict__ off, const int* __restrict__ bsum, int N) {
    int gid = blockIdx.x * blockDim.x + threadIdx.x;
    if (gid < N) off[gid] += bsum[gid / SCAN_BLK];
}
__global__ void scatter_kernel(const int* __restrict__ esrc,
                               const int* __restrict__ edst,
                               const float* __restrict__ ew,
                               const int* __restrict__ off,
                               const int* __restrict__ rank,
                               int* __restrict__ src_s,
                               float* __restrict__ w_s, int E) {
    int e = blockIdx.x * blockDim.x + threadIdx.x;
    if (e < E) {
        int pos = off[edst[e]] + rank[e];
        src_s[pos] = esrc[e];
        w_s[pos] = ew[e];
    }
}

// ---------------------------------------------------------------------------
// Aggregate: one warp per dst node; supp is fp16 (16B = 8 cols per lane).
// Accumulation in fp32; out = segment_sum + bias (fp32).
// ---------------------------------------------------------------------------
__global__ __launch_bounds__(256) void agg_kernel(
    const __half* __restrict__ supp,
    const int* __restrict__ src_s,
    const float* __restrict__ w_s,
    const int* __restrict__ off,
    const float* __restrict__ bias,
    float* __restrict__ out,
    int N, int E) {

    const int warp = (blockIdx.x * blockDim.x + threadIdx.x) >> 5;
    const int lane = threadIdx.x & 31;
    if (warp >= N) return;

    const int beg = off[warp];
    const int end = (warp + 1 < N) ? off[warp + 1] : E;

    const float4* bias4 = reinterpret_cast<const float4*>(bias);
    float4 acc0 = bias4[lane * 2];      // cols lane*8 .. lane*8+3
    float4 acc1 = bias4[lane * 2 + 1];  // cols lane*8+4 .. lane*8+7

    for (int j = beg; j < end; ++j) {
        const int src = __ldg(&src_s[j]);
        const float w = __ldg(&w_s[j]);
        // one uint4 = 8 halves = this lane's 8 columns
        uint4 v = __ldg(reinterpret_cast<const uint4*>(supp + (size_t)src * N_DIM) + lane);
        float2 f0 = __half22float2(*reinterpret_cast<__half2*>(&v.x));
        float2 f1 = __half22float2(*reinterpret_cast<__half2*>(&v.y));
        float2 f2 = __half22float2(*reinterpret_cast<__half2*>(&v.z));
        float2 f3 = __half22float2(*reinterpret_cast<__half2*>(&v.w));
        acc0.x = fmaf(f0.x, w, acc0.x); acc0.y = fmaf(f0.y, w, acc0.y);
        acc0.z = fmaf(f1.x, w, acc0.z); acc0.w = fmaf(f1.y, w, acc0.w);
        acc1.x = fmaf(f2.x, w, acc1.x); acc1.y = fmaf(f2.y, w, acc1.y);
        acc1.z = fmaf(f3.x, w, acc1.z); acc1.w = fmaf(f3.y, w, acc1.w);
    }

    float4* drow = reinterpret_cast<float4*>(out + (size_t)warp * N_DIM);
    drow[lane * 2] = acc0;
    drow[lane * 2 + 1] = acc1;
}

// ---------------------------------------------------------------------------
// GEMM: single-product fp16, BM=128, BN=128, BK=32, double-buffer, occ 2
// (128 regs/thread, no spills). Epilogue stores supp as fp16.
// ---------------------------------------------------------------------------
#define BK2 32
#define ROWB 80
#define T128 (128 * ROWB)
#define O_AH 0
#define O_BH (T128)
#define STG (2 * T128)                /* 20480 */
#define GEMM_SMEM (2 * STG)           /* 40960 */

__global__ __launch_bounds__(256, 2) void gemm_f16_kernel(
    const float* __restrict__ x,
    const __half* __restrict__ wh,
    __half* __restrict__ supp, int M) {

    extern __shared__ __align__(128) char smem[];
    const uint32_t sbase = smem_u32(smem);

    const int tid = threadIdx.x;
    const int wid = tid >> 5;
    const int lane = tid & 31;
    const int rowBase = blockIdx.y * 128;
    const int colBase = blockIdx.x * 128;

    const int warp_m = (wid >> 2) * 64;
    const int warp_n = (wid & 3) * 32;

    const int ld_row = tid >> 1;
    const int ld_kc  = (tid & 1) * 16;
    const int a_grow = rowBase + ld_row;
    const bool a_ok = (a_grow < M);
    const float4* x4 = reinterpret_cast<const float4*>(x);

    const int a_lr = lane & 15;
    const int a_lk = (lane >> 4) * 8;
    const int b_ln = ((lane >> 4) * 8) + (lane & 7);
    const int b_lk = ((lane >> 3) & 1) * 8;

    float acc[4][4][4];
#pragma unroll
    for (int i = 0; i < 4; i++)
#pragma unroll
        for (int j = 0; j < 4; j++)
#pragma unroll
            for (int q = 0; q < 4; q++) acc[i][j][q] = 0.0f;

    float4 ga[4];

    auto load_A = [&](int c) {
        const int k0 = c * BK2;
#pragma unroll
        for (int j = 0; j < 4; j++) {
            ga[j] = a_ok ? x4[(size_t)a_grow * (K_DIM / 4) + ((k0 + ld_kc) >> 2) + j]
                         : make_float4(0.f, 0.f, 0.f, 0.f);
        }
    };
    auto store_A = [&](int s) {
        const uint32_t st = sbase + s * STG;
        uint32_t a_off = (uint32_t)ld_row * ROWB + ld_kc * 2;
#pragma unroll
        for (int j = 0; j < 4; j++) {
            uint32_t h0 = pack_h2(ga[j].x, ga[j].y);
            uint32_t h1 = pack_h2(ga[j].z, ga[j].w);
            asm volatile("st.shared.v2.b32 [%0], {%1, %2};"
                         :: "r"(st + O_AH + a_off + j * 8), "r"(h0), "r"(h1) : "memory");
        }
    };
    auto issue_B = [&](int s, int c) {
        const int k0 = c * BK2;
        const uint32_t st = sbase + s * STG;
        // 128 rows x 4 16B-chunks = 512 chunks; 256 threads -> 2 each
#pragma unroll
        for (int i = 0; i < 2; i++) {
            int a = tid + i * 256;
            int row = a >> 2, cc = a & 3;
            const __half* sh = wh + (size_t)(colBase + row) * K_DIM + k0 + cc * 8;
            cp16(st + O_BH + row * ROWB + cc * 16, sh);
        }
        CP_COMMIT();
    };

    auto compute = [&](int s) {
        const uint32_t st = sbase + s * STG;
#pragma unroll
        for (int ks = 0; ks < 2; ks++) {
            uint32_t ah[4][4];
#pragma unroll
            for (int mi = 0; mi < 4; mi++) {
                uint32_t off = (uint32_t)(warp_m + mi * 16 + a_lr) * ROWB +
                               (ks * 16 + a_lk) * 2;
                ldm_x4(st + O_AH + off, ah[mi]);
            }
#pragma unroll
            for (int pi = 0; pi < 2; pi++) {
                uint32_t off = (uint32_t)(warp_n + pi * 16 + b_ln) * ROWB +
                               (ks * 16 + b_lk) * 2;
                uint32_t bh[4];
                ldm_x4(st + O_BH + off, bh);
#pragma unroll
                for (int mi = 0; mi < 4; mi++) {
                    mma_f16(acc[mi][pi * 2 + 0], ah[mi], bh[0], bh[1]);
                    mma_f16(acc[mi][pi * 2 + 1], ah[mi], bh[2], bh[3]);
                }
            }
        }
    };

    // prologue
    load_A(0);
    store_A(0);
    issue_B(0, 0);

#pragma unroll 1
    for (int c = 0; c < K_DIM / BK2; ++c) {
        const bool more = (c + 1 < K_DIM / BK2);
        CP_WAIT(0);                    // B(c) landed
        __syncthreads();
        if (more) {
            load_A(c + 1);             // LDG overlaps compute(c)
            issue_B((c + 1) & 1, c + 1);
        }
        compute(c & 1);
        if (more) store_A((c + 1) & 1);
    }

    // epilogue: convert to fp16, store (half2 per 2 cols)
    const int lrow = lane >> 2;
    const int lcol = (lane & 3) * 2;
#pragma unroll
    for (int mi = 0; mi < 4; mi++) {
#pragma unroll
        for (int half = 0; half < 2; half++) {
            int grow = rowBase + warp_m + mi * 16 + lrow + half * 8;
            if (grow < M) {
                __half* dst = supp + (size_t)grow * N_DIM + colBase + warp_n;
#pragma unroll
                for (int ni = 0; ni < 4; ni++) {
                    uint32_t h = half ? pack_h2(acc[mi][ni][2], acc[mi][ni][3])
                                      : pack_h2(acc[mi][ni][0], acc[mi][ni][1]);
                    *reinterpret_cast<uint32_t*>(dst + ni * 8 + lcol) = h;
                }
            }
        }
    }
}

// ---------------------------------------------------------------------------
// Launch — CSR build forked on side stream, overlapped with convert+GEMM.
// ---------------------------------------------------------------------------
extern "C" void kernel_launch(void* const* d_in, const int* in_sizes, int n_in,
                              void* d_out, int out_size) {
    const float* x      = (const float*)d_in[0];
    const float* weight = (const float*)d_in[1];
    const float* bias   = (const float*)d_in[2];
    const float* ew     = (const float*)d_in[3];
    const int*   esrc   = (const int*)d_in[4];
    const int*   edst   = (const int*)d_in[5];
    float* out = (float*)d_out;

    const int M = in_sizes[0] / K_DIM;   // 100000
    const int E = in_sizes[3];           // 800000

    __half* supp;         cudaGetSymbolAddress((void**)&supp, g_supp);
    __half* wh;           cudaGetSymbolAddress((void**)&wh, g_wh);
    int* deg;             cudaGetSymbolAddress((void**)&deg, g_deg);
    int* off;             cudaGetSymbolAddress((void**)&off, g_off);
    int* rank;            cudaGetSymbolAddress((void**)&rank, g_rank);
    int* bsum;            cudaGetSymbolAddress((void**)&bsum, g_bsum);
    int* src_s;           cudaGetSymbolAddress((void**)&src_s, g_src_s);
    float* w_s;           cudaGetSymbolAddress((void**)&w_s, g_w_s);

    static cudaStream_t s_side = nullptr;
    static cudaEvent_t  s_fork = nullptr, s_join = nullptr;
    static bool s_init = false;
    if (!s_init) {
        cudaFuncSetAttribute(gemm_f16_kernel,
                             cudaFuncAttributeMaxDynamicSharedMemorySize, GEMM_SMEM);
        cudaStreamCreateWithFlags(&s_side, cudaStreamNonBlocking);
        cudaEventCreateWithFlags(&s_fork, cudaEventDisableTiming);
        cudaEventCreateWithFlags(&s_join, cudaEventDisableTiming);
        s_init = true;
    }

    const int nblk_scan = (M + SCAN_BLK - 1) / SCAN_BLK;

    // Fork
    cudaEventRecord(s_fork, 0);
    cudaStreamWaitEvent(s_side, s_fork, 0);

    // side stream: CSR build
    zero_deg_kernel<<<(M + 255) / 256, 256, 0, s_side>>>(deg, M);
    hist_rank_kernel<<<(E + 255) / 256, 256, 0, s_side>>>(edst, deg, rank, E);
    scan1_kernel<<<nblk_scan, SCAN_BLK, 0, s_side>>>(deg, off, bsum, M);
    scan2_kernel<<<1, SCAN_BLK, 0, s_side>>>(bsum, nblk_scan);
    scan3_kernel<<<(M + 255) / 256, 256, 0, s_side>>>(off, bsum, M);
    scatter_kernel<<<(E + 255) / 256, 256, 0, s_side>>>(esrc, edst, ew, off, rank,
                                                        src_s, w_s, E);
    cudaEventRecord(s_join, s_side);

    // main stream: convert W, GEMM
    convert_w_kernel<<<K_DIM, N_DIM>>>(weight, wh);
    {
        dim3 grid(N_DIM / 128, (M + 127) / 128);
        gemm_f16_kernel<<<grid, 256, GEMM_SMEM>>>(x, wh, supp, M);
    }

    // Join, then aggregate
    cudaStreamWaitEvent(0, s_join, 0);
    {
        int blocks = (M + 7) / 8;
        agg_kernel<<<blocks, 256>>>(supp, src_s, w_s, off, bias, out, M, E);
    }
}

// round 14
// speedup vs baseline: 2.0482x; 1.0361x over previous
#include <cuda_runtime.h>
#include <cuda_fp16.h>
#include <cstdint>

#define K_DIM 256
#define N_DIM 256
#define MAX_NODES 100000
#define MAX_EDGES 800000
#define SCAN_BLK 1024
#define MAX_SCAN_BLOCKS ((MAX_NODES + SCAN_BLK - 1) / SCAN_BLK)

// Static device scratch (allocation-free rule)
__device__ __half g_supp[(size_t)MAX_NODES * N_DIM];   // fp16 supp: halves agg traffic
__device__ __half g_wh[K_DIM * N_DIM];                 // W fp16, B-operand layout [n][k]
__device__ int   g_deg[MAX_NODES];
__device__ int   g_off[MAX_NODES];
__device__ int   g_rank[MAX_EDGES];
__device__ int   g_bsum[MAX_SCAN_BLOCKS];
__device__ int   g_src_s[MAX_EDGES];
__device__ float g_w_s[MAX_EDGES];

// ---------------------------------------------------------------------------
// helpers
// ---------------------------------------------------------------------------
__device__ __forceinline__ uint32_t smem_u32(const void* p) {
    uint32_t a;
    asm("{ .reg .u64 t; cvta.to.shared.u64 t, %1; cvt.u32.u64 %0, t; }" : "=r"(a) : "l"(p));
    return a;
}
__device__ __forceinline__ void cp16(uint32_t dst, const void* src) {
    asm volatile("cp.async.cg.shared.global [%0], [%1], 16;"
                 :: "r"(dst), "l"(src) : "memory");
}
#define CP_COMMIT() asm volatile("cp.async.commit_group;" ::: "memory")
#define CP_WAIT(n)  asm volatile("cp.async.wait_group %0;" :: "n"(n) : "memory")

__device__ __forceinline__ void ldm_x4(uint32_t addr, uint32_t r[4]) {
    asm volatile("ldmatrix.sync.aligned.m8n8.x4.shared.b16 {%0,%1,%2,%3}, [%4];"
                 : "=r"(r[0]), "=r"(r[1]), "=r"(r[2]), "=r"(r[3]) : "r"(addr));
}
__device__ __forceinline__ void mma_f16(float c[4], const uint32_t a[4],
                                        uint32_t b0, uint32_t b1) {
    asm volatile(
        "mma.sync.aligned.m16n8k16.row.col.f32.f16.f16.f32 "
        "{%0,%1,%2,%3}, {%4,%5,%6,%7}, {%8,%9}, {%0,%1,%2,%3};"
        : "+f"(c[0]), "+f"(c[1]), "+f"(c[2]), "+f"(c[3])
        : "r"(a[0]), "r"(a[1]), "r"(a[2]), "r"(a[3]), "r"(b0), "r"(b1));
}
__device__ __forceinline__ uint32_t pack_h2(float x, float y) {
    __half2 h = __floats2half2_rn(x, y);
    return *reinterpret_cast<uint32_t*>(&h);
}

// ---------------------------------------------------------------------------
// Kernel 0: convert + transpose W -> fp16, B-operand layout [n][k]
// ---------------------------------------------------------------------------
__global__ void convert_w_kernel(const float* __restrict__ W,
                                 __half* __restrict__ wh) {
    int k = blockIdx.x;
    int n = threadIdx.x;
    wh[n * K_DIM + k] = __float2half(W[k * N_DIM + n]);
}

// ---------------------------------------------------------------------------
// CSR build: zero -> hist(+rank) -> scan(3) -> scatter
// ---------------------------------------------------------------------------
__global__ void zero_deg_kernel(int* __restrict__ deg, int N) {
    int i = blockIdx.x * blockDim.x + threadIdx.x;
    if (i < N) deg[i] = 0;
}
__global__ void hist_rank_kernel(const int* __restrict__ edst,
                                 int* __restrict__ deg,
                                 int* __restrict__ rank, int E) {
    int i = blockIdx.x * blockDim.x + threadIdx.x;
    if (i < E) rank[i] = atomicAdd(&deg[edst[i]], 1);
}
__global__ __launch_bounds__(SCAN_BLK) void scan1_kernel(
    const int* __restrict__ deg, int* __restrict__ off, int* __restrict__ bsum, int N) {
    __shared__ int s[SCAN_BLK];
    int tid = threadIdx.x;
    int gid = blockIdx.x * SCAN_BLK + tid;
    int v = (gid < N) ? deg[gid] : 0;
    s[tid] = v;
    __syncthreads();
#pragma unroll
    for (int d = 1; d < SCAN_BLK; d <<= 1) {
        int t = (tid >= d) ? s[tid - d] : 0;
        __syncthreads();
        s[tid] += t;
        __syncthreads();
    }
    if (gid < N) off[gid] = s[tid] - v;
    if (tid == SCAN_BLK - 1) bsum[blockIdx.x] = s[tid];
}
__global__ __launch_bounds__(SCAN_BLK) void scan2_kernel(int* __restrict__ bsum, int nb) {
    __shared__ int s[SCAN_BLK];
    int tid = threadIdx.x;
    int v = (tid < nb) ? bsum[tid] : 0;
    s[tid] = v;
    __syncthreads();
#pragma unroll
    for (int d = 1; d < SCAN_BLK; d <<= 1) {
        int t = (tid >= d) ? s[tid - d] : 0;
        __syncthreads();
        s[tid] += t;
        __syncthreads();
    }
    if (tid < nb) bsum[tid] = s[tid] - v;
}
__global__ void scan3_kernel(int* __restrict__ off, const int* __restrict__ bsum, int N) {
    int gid = blockIdx.x * blockDim.x + threadIdx.x;
    if (gid < N) off[gid] += bsum[gid / SCAN_BLK];
}
__global__ void scatter_kernel(const int* __restrict__ esrc,
                               const int* __restrict__ edst,
                               const float* __restrict__ ew,
                               const int* __restrict__ off,
                               const int* __restrict__ rank,
                               int* __restrict__ src_s,
                               float* __restrict__ w_s, int E) {
    int e = blockIdx.x * blockDim.x + threadIdx.x;
    if (e < E) {
        int pos = off[edst[e]] + rank[e];
        src_s[pos] = esrc[e];
        w_s[pos] = ew[e];
    }
}

// ---------------------------------------------------------------------------
// Aggregate: one warp per dst node; supp fp16 (one uint4 = 8 cols per lane);
// fp32 accumulation; out = segment_sum + bias (fp32).
// ---------------------------------------------------------------------------
__global__ __launch_bounds__(256) void agg_kernel(
    const __half* __restrict__ supp,
    const int* __restrict__ src_s,
    const float* __restrict__ w_s,
    const int* __restrict__ off,
    const float* __restrict__ bias,
    float* __restrict__ out,
    int N, int E) {

    const int warp = (blockIdx.x * blockDim.x + threadIdx.x) >> 5;
    const int lane = threadIdx.x & 31;
    if (warp >= N) return;

    const int beg = off[warp];
    const int end = (warp + 1 < N) ? off[warp + 1] : E;

    const float4* bias4 = reinterpret_cast<const float4*>(bias);
    float4 acc0 = bias4[lane * 2];
    float4 acc1 = bias4[lane * 2 + 1];

    for (int j = beg; j < end; ++j) {
        const int src = __ldg(&src_s[j]);
        const float w = __ldg(&w_s[j]);
        uint4 v = __ldg(reinterpret_cast<const uint4*>(supp + (size_t)src * N_DIM) + lane);
        float2 f0 = __half22float2(*reinterpret_cast<__half2*>(&v.x));
        float2 f1 = __half22float2(*reinterpret_cast<__half2*>(&v.y));
        float2 f2 = __half22float2(*reinterpret_cast<__half2*>(&v.z));
        float2 f3 = __half22float2(*reinterpret_cast<__half2*>(&v.w));
        acc0.x = fmaf(f0.x, w, acc0.x); acc0.y = fmaf(f0.y, w, acc0.y);
        acc0.z = fmaf(f1.x, w, acc0.z); acc0.w = fmaf(f1.y, w, acc0.w);
        acc1.x = fmaf(f2.x, w, acc1.x); acc1.y = fmaf(f2.y, w, acc1.y);
        acc1.z = fmaf(f3.x, w, acc1.z); acc1.w = fmaf(f3.y, w, acc1.w);
    }

    float4* drow = reinterpret_cast<float4*>(out + (size_t)warp * N_DIM);
    drow[lane * 2] = acc0;
    drow[lane * 2 + 1] = acc1;
}

// ---------------------------------------------------------------------------
// GEMM: single-product fp16, BM=128, BN=256 (full width: x read ONCE),
// BK=32, 512 threads (16 warps, 2x8), double-buffer.
// ---------------------------------------------------------------------------
#define BK2 32
#define ROWB 80
#define A_TILE (128 * ROWB)           /* 10240 */
#define B_TILE (256 * ROWB)           /* 20480 */
#define O_AH 0
#define O_BH (A_TILE)
#define STG (A_TILE + B_TILE)         /* 30720 */
#define GEMM_SMEM (2 * STG)           /* 61440 */

__global__ __launch_bounds__(512, 1) void gemm_f16_kernel(
    const float* __restrict__ x,
    const __half* __restrict__ wh,
    __half* __restrict__ supp, int M) {

    extern __shared__ __align__(128) char smem[];
    const uint32_t sbase = smem_u32(smem);

    const int tid = threadIdx.x;
    const int wid = tid >> 5;
    const int lane = tid & 31;
    const int rowBase = blockIdx.x * 128;

    const int warp_m = (wid >> 3) * 64;   // 0 or 64
    const int warp_n = (wid & 7) * 32;    // 0..224

    // A mapping: 128 rows x 32 f32 cols; 512 threads -> 8 f32 (2 float4) each
    const int ld_row = tid >> 2;          // 0..127
    const int ld_q   = tid & 3;           // 8-f32 group
    const int a_grow = rowBase + ld_row;
    const bool a_ok = (a_grow < M);
    const float4* x4 = reinterpret_cast<const float4*>(x);

    const int a_lr = lane & 15;
    const int a_lk = (lane >> 4) * 8;
    const int b_ln = ((lane >> 4) * 8) + (lane & 7);
    const int b_lk = ((lane >> 3) & 1) * 8;

    float acc[4][4][4];
#pragma unroll
    for (int i = 0; i < 4; i++)
#pragma unroll
        for (int j = 0; j < 4; j++)
#pragma unroll
            for (int q = 0; q < 4; q++) acc[i][j][q] = 0.0f;

    float4 ga[2];

    auto load_A = [&](int c) {
        const int k0 = c * BK2;
#pragma unroll
        for (int j = 0; j < 2; j++) {
            ga[j] = a_ok ? x4[(size_t)a_grow * (K_DIM / 4) + ((k0 + ld_q * 8) >> 2) + j]
                         : make_float4(0.f, 0.f, 0.f, 0.f);
        }
    };
    auto store_A = [&](int s) {
        const uint32_t st = sbase + s * STG;
        uint32_t a_off = (uint32_t)ld_row * ROWB + ld_q * 16;
        uint32_t h0 = pack_h2(ga[0].x, ga[0].y);
        uint32_t h1 = pack_h2(ga[0].z, ga[0].w);
        uint32_t h2 = pack_h2(ga[1].x, ga[1].y);
        uint32_t h3 = pack_h2(ga[1].z, ga[1].w);
        asm volatile("st.shared.v4.b32 [%0], {%1, %2, %3, %4};"
                     :: "r"(st + O_AH + a_off), "r"(h0), "r"(h1), "r"(h2), "r"(h3)
                     : "memory");
    };
    auto issue_B = [&](int s, int c) {
        const int k0 = c * BK2;
        const uint32_t st = sbase + s * STG;
        // 256 rows x 4 16B-chunks = 1024 chunks; 512 threads -> 2 each
#pragma unroll
        for (int i = 0; i < 2; i++) {
            int a = tid + i * 512;
            int row = a >> 2, cc = a & 3;
            const __half* sh = wh + (size_t)row * K_DIM + k0 + cc * 8;
            cp16(st + O_BH + row * ROWB + cc * 16, sh);
        }
        CP_COMMIT();
    };

    auto compute = [&](int s) {
        const uint32_t st = sbase + s * STG;
#pragma unroll
        for (int ks = 0; ks < 2; ks++) {
            uint32_t ah[4][4];
#pragma unroll
            for (int mi = 0; mi < 4; mi++) {
                uint32_t off = (uint32_t)(warp_m + mi * 16 + a_lr) * ROWB +
                               (ks * 16 + a_lk) * 2;
                ldm_x4(st + O_AH + off, ah[mi]);
            }
#pragma unroll
            for (int pi = 0; pi < 2; pi++) {
                uint32_t off = (uint32_t)(warp_n + pi * 16 + b_ln) * ROWB +
                               (ks * 16 + b_lk) * 2;
                uint32_t bh[4];
                ldm_x4(st + O_BH + off, bh);
#pragma unroll
                for (int mi = 0; mi < 4; mi++) {
                    mma_f16(acc[mi][pi * 2 + 0], ah[mi], bh[0], bh[1]);
                    mma_f16(acc[mi][pi * 2 + 1], ah[mi], bh[2], bh[3]);
                }
            }
        }
    };

    // prologue
    load_A(0);
    store_A(0);
    issue_B(0, 0);

#pragma unroll 1
    for (int c = 0; c < K_DIM / BK2; ++c) {
        const bool more = (c + 1 < K_DIM / BK2);
        CP_WAIT(0);                    // B(c) landed
        __syncthreads();
        if (more) {
            load_A(c + 1);             // LDG overlaps compute(c)
            issue_B((c + 1) & 1, c + 1);
        }
        compute(c & 1);
        if (more) store_A((c + 1) & 1);
    }

    // epilogue: fp16 stores
    const int lrow = lane >> 2;
    const int lcol = (lane & 3) * 2;
#pragma unroll
    for (int mi = 0; mi < 4; mi++) {
#pragma unroll
        for (int half = 0; half < 2; half++) {
            int grow = rowBase + warp_m + mi * 16 + lrow + half * 8;
            if (grow < M) {
                __half* dst = supp + (size_t)grow * N_DIM + warp_n;
#pragma unroll
                for (int ni = 0; ni < 4; ni++) {
                    uint32_t h = half ? pack_h2(acc[mi][ni][2], acc[mi][ni][3])
                                      : pack_h2(acc[mi][ni][0], acc[mi][ni][1]);
                    *reinterpret_cast<uint32_t*>(dst + ni * 8 + lcol) = h;
                }
            }
        }
    }
}

// ---------------------------------------------------------------------------
// Launch — CSR build forked on side stream, overlapped with convert+GEMM.
// ---------------------------------------------------------------------------
extern "C" void kernel_launch(void* const* d_in, const int* in_sizes, int n_in,
                              void* d_out, int out_size) {
    const float* x      = (const float*)d_in[0];
    const float* weight = (const float*)d_in[1];
    const float* bias   = (const float*)d_in[2];
    const float* ew     = (const float*)d_in[3];
    const int*   esrc   = (const int*)d_in[4];
    const int*   edst   = (const int*)d_in[5];
    float* out = (float*)d_out;

    const int M = in_sizes[0] / K_DIM;   // 100000
    const int E = in_sizes[3];           // 800000

    __half* supp;         cudaGetSymbolAddress((void**)&supp, g_supp);
    __half* wh;           cudaGetSymbolAddress((void**)&wh, g_wh);
    int* deg;             cudaGetSymbolAddress((void**)&deg, g_deg);
    int* off;             cudaGetSymbolAddress((void**)&off, g_off);
    int* rank;            cudaGetSymbolAddress((void**)&rank, g_rank);
    int* bsum;            cudaGetSymbolAddress((void**)&bsum, g_bsum);
    int* src_s;           cudaGetSymbolAddress((void**)&src_s, g_src_s);
    float* w_s;           cudaGetSymbolAddress((void**)&w_s, g_w_s);

    static cudaStream_t s_side = nullptr;
    static cudaEvent_t  s_fork = nullptr, s_join = nullptr;
    static bool s_init = false;
    if (!s_init) {
        cudaFuncSetAttribute(gemm_f16_kernel,
                             cudaFuncAttributeMaxDynamicSharedMemorySize, GEMM_SMEM);
        cudaStreamCreateWithFlags(&s_side, cudaStreamNonBlocking);
        cudaEventCreateWithFlags(&s_fork, cudaEventDisableTiming);
        cudaEventCreateWithFlags(&s_join, cudaEventDisableTiming);
        s_init = true;
    }

    const int nblk_scan = (M + SCAN_BLK - 1) / SCAN_BLK;

    // Fork
    cudaEventRecord(s_fork, 0);
    cudaStreamWaitEvent(s_side, s_fork, 0);

    // side stream: CSR build
    zero_deg_kernel<<<(M + 255) / 256, 256, 0, s_side>>>(deg, M);
    hist_rank_kernel<<<(E + 255) / 256, 256, 0, s_side>>>(edst, deg, rank, E);
    scan1_kernel<<<nblk_scan, SCAN_BLK, 0, s_side>>>(deg, off, bsum, M);
    scan2_kernel<<<1, SCAN_BLK, 0, s_side>>>(bsum, nblk_scan);
    scan3_kernel<<<(M + 255) / 256, 256, 0, s_side>>>(off, bsum, M);
    scatter_kernel<<<(E + 255) / 256, 256, 0, s_side>>>(esrc, edst, ew, off, rank,
                                                        src_s, w_s, E);
    cudaEventRecord(s_join, s_side);

    // main stream: convert W, GEMM (BN=256: x read once)
    convert_w_kernel<<<K_DIM, N_DIM>>>(weight, wh);
    {
        int grid = (M + 127) / 128;
        gemm_f16_kernel<<<grid, 512, GEMM_SMEM>>>(x, wh, supp, M);
    }

    // Join, then aggregate
    cudaStreamWaitEvent(0, s_join, 0);
    {
        int blocks = (M + 7) / 8;
        agg_kernel<<<blocks, 256>>>(supp, src_s, w_s, off, bias, out, M, E);
    }
}